// round 14
// baseline (speedup 1.0000x reference)
#include <cuda_runtime.h>
#include <cuda_bf16.h>
#include <math.h>
#include <stdint.h>

#define BB 16
#define TT 800
#define EE 512
#define DD 1024
#define AA 512
#define OO 5000
#define LL 97
#define SOSEOS 4999
#define NBLK 148
#define NTH 512

// x staging strides (bf16 elems, +8 pad)
#define XS0 2568   // K0=2560
#define XS1 2056   // K1=2048
#define XSD 1032   // Kd=1024
#define RED_OFF 83968
#define SMEM_BYTES 92160
#define LOGITS_SMEM (32 * (DD + 8) * 2 + 32 * 132 * 4)

// ---------------- scratch ----------------
__device__ __align__(16) unsigned short g_preenc_bf[BB * TT * AA];
__device__ __align__(16) unsigned short g_hs_bf[BB * TT * EE];
__device__ __align__(16) unsigned short g_W0F[4096 * 2560];   // mma B-fragment layouts
__device__ __align__(16) unsigned short g_W1F[4096 * 2048];
__device__ __align__(16) unsigned short g_WdF[512 * 1024];
__device__ __align__(16) unsigned short g_WeF[512 * 512];
__device__ __align__(16) unsigned short g_WoF[5000 * 1024];
__device__ __align__(16) unsigned short g_eys_bf[BB * LL * DD];
__device__ __align__(16) unsigned short g_z0bf[BB * DD], g_z1bf[BB * DD];
__device__ __align__(16) unsigned short g_x1bf[BB * 2048];
__device__ __align__(16) unsigned short g_zallbf[BB * LL * DD];
__device__ float g_attc_f[BB * AA];       // unnormalized context accumulator (fp32 atomics)
__device__ float g_sw[BB];                // sum of softmax weights
__device__ float g_b0[4096], g_b1[4096];
__device__ float g_c0[BB * DD], g_c1[BB * DD];
__device__ float g_dp[BB * AA];
__device__ float g_pm2[BB * LL * 40], g_ps2[BB * LL * 40];
__device__ float g_tgt[BB * LL];
__device__ volatile unsigned g_arr[NBLK];
__device__ volatile unsigned g_rel;

// ---------------- helpers ----------------
__device__ __forceinline__ float tanh_ap(float x) {
    float y; asm("tanh.approx.f32 %0, %1;" : "=f"(y) : "f"(x)); return y;
}
__device__ __forceinline__ float sigm(float x) { return 1.0f / (1.0f + __expf(-x)); }
__device__ __forceinline__ unsigned short f2bf(float v) {
    return __bfloat16_as_ushort(__float2bfloat16_rn(v));
}
__device__ __forceinline__ unsigned pk2bf(float a, float b) {
    return (unsigned)f2bf(a) | ((unsigned)f2bf(b) << 16);
}

// device-wide barrier — PROVEN two-hop version, split into arrive/wait
__device__ __forceinline__ void gbar_arrive(unsigned ep) {
    __syncthreads();
    if (threadIdx.x == 0) {
        __threadfence();
        g_arr[blockIdx.x] = ep;
    }
    if (blockIdx.x == 0) {
        if (threadIdx.x < NBLK) {
            while (g_arr[threadIdx.x] < ep) { }
        }
        __syncthreads();
        if (threadIdx.x == 0) { __threadfence(); g_rel = ep; }
    }
}
__device__ __forceinline__ void gbar_wait(unsigned ep) {
    if (threadIdx.x == 0) {
        while (g_rel < ep) { }
        __threadfence();
    }
    __syncthreads();
}
__device__ __forceinline__ void gbar(unsigned ep) {
    gbar_arrive(ep);
    gbar_wait(ep);
}

// ---------------- prolog: pack ALL weights (coalesced, 32 k's / thread) ----------------
// For fixed (j, ktp) the 32 k-elements occupy a contiguous 64-byte run.
__device__ __forceinline__ void pack32(unsigned short* dst, int K, int j, int ktp,
                                       const float* __restrict__ Wa,
                                       const float* __restrict__ Wb, int Ka) {
    int jt = j >> 3, n = j & 7;
    unsigned short buf[32];
    int k0 = ktp * 32;
#pragma unroll
    for (int kk = 0; kk < 32; kk++) {
        int k = k0 + kk;
        float v = (k < Ka) ? Wa[(size_t)j * Ka + k] : Wb[(size_t)j * (K - Ka) + (k - Ka)];
        int kt = k >> 4, k16 = k & 15;
        int lane_off = (k16 & 7) >> 1;
        int comp = ((kt & 1) << 1) + (k16 >> 3);
        buf[lane_off * 8 + comp * 2 + (k16 & 1)] = f2bf(v);
    }
    size_t run = (((size_t)jt * (K >> 5) + ktp) * 32 + n * 4) * 8;
    uint4* d4 = (uint4*)(dst + run);
#pragma unroll
    for (int q = 0; q < 4; q++) d4[q] = ((const uint4*)buf)[q];
}
// per-matrix thread counts (elements/32)
#define P0 327680            // W0: 4096*2560/32
#define P1 (P0 + 262144)     // W1: 4096*2048/32
#define P2C (P1 + 16384)     // Wd: 512*1024/32
#define P3C (P2C + 8192)     // We: 512*512/32
#define P4C (P3C + 160000)   // Wo: 5000*1024/32
__global__ void pack_all(const float* __restrict__ Wih0, const float* __restrict__ Whh0,
                         const float* __restrict__ Wih1, const float* __restrict__ Whh1,
                         const float* __restrict__ Wenc, const float* __restrict__ Wout,
                         const float* __restrict__ Wdec) {
    int i = blockIdx.x * 256 + threadIdx.x;
    if (i < P0) {
        // order: (jt, ktp, n) -> adjacent threads share (jt,ktp), differ in n (coalesced stores)
        int n = i & 7, rest = i >> 3;
        int ktp = rest % 80, jt = rest / 80;     // K=2560 -> K/32=80
        pack32(g_W0F, 2560, jt * 8 + n, ktp, Wih0, Whh0, 1536);
    } else if (i < P1) {
        int q = i - P0;
        int n = q & 7, rest = q >> 3;
        int ktp = rest % 64, jt = rest / 64;     // K=2048 -> 64
        pack32(g_W1F, 2048, jt * 8 + n, ktp, Wih1, Whh1, 1024);
    } else if (i < P2C) {
        int q = i - P1;
        int n = q & 7, rest = q >> 3;
        int ktp = rest % 32, jt = rest / 32;     // K=1024 -> 32
        pack32(g_WdF, 1024, jt * 8 + n, ktp, Wdec, Wdec, 1024);
    } else if (i < P3C) {
        int q = i - P2C;
        int n = q & 7, rest = q >> 3;
        int ktp = rest % 16, jt = rest / 16;     // K=512 -> 16
        pack32(g_WeF, 512, jt * 8 + n, ktp, Wenc, Wenc, 512);
    } else if (i < P4C) {
        int q = i - P3C;
        int n = q & 7, rest = q >> 3;
        int ktp = rest % 32, jt = rest / 32;     // K=1024 -> 32
        pack32(g_WoF, 1024, jt * 8 + n, ktp, Wout, Wout, 1024);
    }
}

// merged small prolog (hs conversion vectorized: 8 elems/thread)
__global__ void prep_all(const float* __restrict__ hs,
                         const float* __restrict__ bih0, const float* __restrict__ bhh0,
                         const float* __restrict__ bih1, const float* __restrict__ bhh1,
                         const int* __restrict__ ys_pad, const float* __restrict__ embed) {
    int idx = blockIdx.x * 256 + threadIdx.x;
    if (idx < (BB * TT * EE) / 8) {
        const float4* s = (const float4*)hs + (size_t)idx * 2;
        float4 a = s[0], b = s[1];
        uint4 v;
        v.x = pk2bf(a.x, a.y); v.y = pk2bf(a.z, a.w);
        v.z = pk2bf(b.x, b.y); v.w = pk2bf(b.z, b.w);
        ((uint4*)g_hs_bf)[idx] = v;
    }
    if (idx < 4096) {
        g_b0[idx] = bih0[idx] + bhh0[idx];
        g_b1[idx] = bih1[idx] + bhh1[idx];
    }
    if (idx < BB * DD) {
        g_c0[idx] = 0.f; g_c1[idx] = 0.f;
        g_z0bf[idx] = 0; g_z1bf[idx] = 0;
    }
    if (idx < BB * AA) { g_dp[idx] = 0.f; g_attc_f[idx] = 0.f; }
    if (idx < BB) g_sw[idx] = 0.f;
    if (idx < NBLK) g_arr[idx] = 0u;
    if (idx == 0) g_rel = 0u;
    if (idx < BB * LL * DD) {
        int m = idx >> 10, d = idx & 1023;
        int b = m / LL, l = m % LL;
        int tok = (l == 0) ? SOSEOS : ys_pad[b * 96 + l - 1];
        g_eys_bf[idx] = f2bf(embed[(size_t)tok * DD + d]);
    }
}

// ---------------- warp-level mma over one n8 tile, k-slice ----------------
__device__ __forceinline__ void warp_mma(const uint4* __restrict__ wf, int KT32, int jt,
                                         int ktp0, int nktp, const unsigned short* xs,
                                         int XSTR, int lane, float* c) {
    int m = lane >> 3, r = lane & 7;
    int row = r + ((m & 1) << 3);
    int colh = m >> 1;
    unsigned sbase = (unsigned)__cvta_generic_to_shared(xs) + (unsigned)((row * XSTR + colh * 8) * 2);
    const uint4* wp = wf + (size_t)jt * KT32 * 32 + lane;
#pragma unroll 4
    for (int t = 0; t < nktp; t++) {
        int ktp = ktp0 + t;
        unsigned a0,a1,a2,a3, e0,e1,e2,e3;
        unsigned addr0 = sbase + (unsigned)(ktp * 64);
        asm volatile("ldmatrix.sync.aligned.m8n8.x4.shared.b16 {%0,%1,%2,%3}, [%4];"
            : "=r"(a0),"=r"(a1),"=r"(a2),"=r"(a3) : "r"(addr0));
        asm volatile("ldmatrix.sync.aligned.m8n8.x4.shared.b16 {%0,%1,%2,%3}, [%4];"
            : "=r"(e0),"=r"(e1),"=r"(e2),"=r"(e3) : "r"(addr0 + 32u));
        uint4 wv = wp[(size_t)ktp * 32];
        asm volatile("mma.sync.aligned.m16n8k16.row.col.f32.bf16.bf16.f32 "
            "{%0,%1,%2,%3}, {%4,%5,%6,%7}, {%8,%9}, {%0,%1,%2,%3};"
            : "+f"(c[0]),"+f"(c[1]),"+f"(c[2]),"+f"(c[3])
            : "r"(a0),"r"(a1),"r"(a2),"r"(a3), "r"(wv.x),"r"(wv.y));
        asm volatile("mma.sync.aligned.m16n8k16.row.col.f32.bf16.bf16.f32 "
            "{%0,%1,%2,%3}, {%4,%5,%6,%7}, {%8,%9}, {%0,%1,%2,%3};"
            : "+f"(c[0]),"+f"(c[1]),"+f"(c[2]),"+f"(c[3])
            : "r"(e0),"r"(e1),"r"(e2),"r"(e3), "r"(wv.z),"r"(wv.w));
    }
}

// ---------------- tensor-core GEMM (pre_enc): Cbf[M,N] = A x Bfrag^T + bias ----------------
template <int MSL, int STORE_BF>
__global__ __launch_bounds__(512) void gemm_mma(const unsigned short* __restrict__ A,
        const uint4* __restrict__ BF, const float* __restrict__ bias,
        float* __restrict__ C, unsigned short* __restrict__ Cbf,
        int M, int N, int K) {
    extern __shared__ __align__(16) unsigned short xsd[];
    const int XSTR = K + 8;
    const int tid = threadIdx.x, lane = tid & 31, wid = tid >> 5;
    const int MT = MSL * 16, NTILE = 16 / MSL;
    int m0 = blockIdx.y * MT;
    int n0 = blockIdx.x * NTILE * 8;
    int kq = K >> 3;
    const uint4* Ag = (const uint4*)A;
    for (int i = tid; i < MT * kq; i += 512) {
        int r = i / kq, q = i - r * kq;
        ((uint4*)(xsd + r * XSTR))[q] = Ag[(size_t)(m0 + r) * kq + q];
    }
    __syncthreads();
    int mi = wid / NTILE, nj = wid % NTILE;
    int jt = (n0 >> 3) + nj;
    if (jt * 8 < N) {
        float c[4] = {0.f, 0.f, 0.f, 0.f};
        warp_mma(BF, K >> 5, jt, 0, K >> 5, xsd + mi * 16 * XSTR, XSTR, lane, c);
        int row0 = m0 + mi * 16;
#pragma unroll
        for (int r = 0; r < 4; r++) {
            int row = row0 + (lane >> 2) + 8 * (r >> 1);
            int col = jt * 8 + (lane & 3) * 2 + (r & 1);
            if (col < N) {
                float v = c[r] + bias[col];
                if (STORE_BF) Cbf[(size_t)row * N + col] = f2bf(v);
                else          C[(size_t)row * N + col] = v;
            }
        }
    }
}

// ---------------- fused logits GEMM + partial logsumexp NLL (32 rows x 128 cols/block) ----------------
__global__ __launch_bounds__(512) void gemm_logits_nll(const unsigned short* __restrict__ A,
        const uint4* __restrict__ BF, const float* __restrict__ bias,
        const int* __restrict__ ys_pad) {
    extern __shared__ __align__(16) unsigned short xsd[];
    const int XSTR = DD + 8;                       // 1032
    float* sl = (float*)(xsd + 32 * XSTR);         // [32][132] fp32
    const int tid = threadIdx.x, lane = tid & 31, wid = tid >> 5;
    int m0 = blockIdx.y * 32, bx = blockIdx.x;
    const uint4* Ag = (const uint4*)A;
    for (int i = tid; i < 32 * 128; i += 512) {
        int r = i >> 7, q = i & 127;
        int row = min(m0 + r, BB * LL - 1);
        ((uint4*)(xsd + r * XSTR))[q] = Ag[(size_t)row * 128 + q];
    }
    __syncthreads();
    int mi = wid >> 3, nj = wid & 7;
    const unsigned short* xrow = xsd + mi * 16 * XSTR;
#pragma unroll
    for (int tt = 0; tt < 2; tt++) {
        int jt = bx * 16 + nj * 2 + tt;
        float c[4] = {0.f, 0.f, 0.f, 0.f};
        if (jt * 8 < OO)
            warp_mma(BF, 32, jt, 0, 32, xrow, XSTR, lane, c);
#pragma unroll
        for (int r = 0; r < 4; r++) {
            int row = mi * 16 + (lane >> 2) + 8 * (r >> 1);
            int coll = (nj * 2 + tt) * 8 + (lane & 3) * 2 + (r & 1);
            int gcol = bx * 128 + coll;
            sl[row * 132 + coll] = (gcol < OO) ? c[r] + bias[gcol] : -1e30f;
        }
    }
    __syncthreads();
#pragma unroll
    for (int rr2 = 0; rr2 < 2; rr2++) {
        int row = wid * 2 + rr2;     // 32 rows over 16 warps
        float v[4];
#pragma unroll
        for (int i = 0; i < 4; i++) v[i] = sl[row * 132 + lane * 4 + i];
        float mx = fmaxf(fmaxf(v[0], v[1]), fmaxf(v[2], v[3]));
#pragma unroll
        for (int o = 16; o; o >>= 1) mx = fmaxf(mx, __shfl_xor_sync(~0u, mx, o));
        float s = __expf(v[0] - mx) + __expf(v[1] - mx) + __expf(v[2] - mx) + __expf(v[3] - mx);
#pragma unroll
        for (int o = 16; o; o >>= 1) s += __shfl_xor_sync(~0u, s, o);
        int grow = m0 + row;
        if (lane == 0 && grow < BB * LL) {
            g_pm2[grow * 40 + bx] = mx;
            g_ps2[grow * 40 + bx] = s;
            int b = grow / LL, l = grow % LL;
            int tgt = (l < 96) ? ys_pad[b * 96 + l] : SOSEOS;
            if (tgt >= bx * 128 && tgt < bx * 128 + 128)
                g_tgt[grow] = sl[row * 132 + (tgt - bx * 128)];
        }
    }
}

__global__ __launch_bounds__(512) void finalize_nll(float* out) {
    __shared__ float red[512];
    int tid = threadIdx.x;
    float acc = 0.f;
    for (int row = tid; row < BB * LL; row += 512) {
        float M = -1e30f;
#pragma unroll 8
        for (int j = 0; j < 40; j++) M = fmaxf(M, g_pm2[row * 40 + j]);
        float S = 0.f;
#pragma unroll 8
        for (int j = 0; j < 40; j++) S += g_ps2[row * 40 + j] * __expf(g_pm2[row * 40 + j] - M);
        acc += logf(S) + M - g_tgt[row];
    }
    red[tid] = acc; __syncthreads();
    for (int s = 256; s; s >>= 1) { if (tid < s) red[tid] += red[tid + s]; __syncthreads(); }
    if (tid == 0) out[0] = red[0] * (96.0f / (float)(BB * LL));
}

// ---------------- persistent decoder loop: 3 phases/step (P2 staging pipelined) ----------------
extern "C" __global__ void __launch_bounds__(NTH, 1)
decoder_loop(const int* __restrict__ hlens, const float* __restrict__ gvec) {
    extern __shared__ __align__(16) char smem[];
    const int bid = blockIdx.x, tid = threadIdx.x;
    const int lane = tid & 31, wid = tid >> 5;
    unsigned ep = 0;

    for (int l = 0; l < LL; l++) {
        // ===== P1: scores + exp (no-max) + unnormalized partial context, all fused =====
        {
            int r0 = bid * 86 + min(bid, 72);
            int nr = 86 + (bid < 72 ? 1 : 0);
            int b0 = r0 / 800;
            bool spans2 = ((r0 + nr - 1) / 800) > b0;
            int hl0 = hlens[b0];
            int hl1 = (b0 + 1 < 16) ? hlens[b0 + 1] : 0;
            unsigned* dp2 = (unsigned*)smem;                  // [2][256] packed bf16x2
            float2* gv2 = (float2*)(smem + 2048);             // [256]
            float* ctxs = (float*)(smem + 4096);              // [2][16][512] fp32
            float* swarr = (float*)(smem + 4096 + 65536);     // [2][16]
            if (tid < 512) {
                int s = tid >> 8, q = tid & 255;
                int bb = b0 + s;
                unsigned pk = 0;
                if (bb < 16) pk = pk2bf(g_dp[bb * 512 + 2 * q], g_dp[bb * 512 + 2 * q + 1]);
                dp2[tid] = pk;
                if (tid < 256) gv2[tid] = make_float2(gvec[2 * tid], gvec[2 * tid + 1]);
            }
            __syncthreads();
            float accA[16], accB[16];
#pragma unroll
            for (int i = 0; i < 16; i++) { accA[i] = 0.f; accB[i] = 0.f; }
            float swA = 0.f, swB = 0.f;
            const unsigned* hsb = (const unsigned*)g_hs_bf;
            for (int r = r0 + wid; r < r0 + nr; r += 16) {
                int b = (r >= (b0 + 1) * 800) ? (b0 + 1) : b0;
                int t = r - b * 800;
                const unsigned* pe = (const unsigned*)g_preenc_bf + (size_t)r * 256;
                const unsigned* dpb = dp2 + (b - b0) * 256;
                float acc = 0.f;
#pragma unroll
                for (int p = 0; p < 8; p++) {
                    int q = lane + 32 * p;
                    unsigned v = pe[q];
                    unsigned d = dpb[q];
                    unsigned sm2, t2;
                    asm("add.rn.bf16x2 %0, %1, %2;" : "=r"(sm2) : "r"(v), "r"(d));
                    asm("tanh.approx.bf16x2 %0, %1;" : "=r"(t2) : "r"(sm2));
                    float lo = __uint_as_float(t2 << 16);
                    float hi = __uint_as_float(t2 & 0xffff0000u);
                    float2 g2 = gv2[q];
                    acc = fmaf(g2.x, lo, fmaf(g2.y, hi, acc));
                }
#pragma unroll
                for (int o = 16; o; o >>= 1) acc += __shfl_xor_sync(~0u, acc, o);
                int hl = (b == b0) ? hl0 : hl1;
                float w = (t < hl) ? __expf(2.0f * acc) : 0.f;
                const unsigned* hp = hsb + (size_t)r * 256;
                if (b == b0) {
                    if (lane == 0) swA += w;
#pragma unroll
                    for (int p = 0; p < 8; p++) {
                        unsigned v = hp[p * 32 + lane];
                        accA[2 * p]     = fmaf(w, __uint_as_float(v << 16), accA[2 * p]);
                        accA[2 * p + 1] = fmaf(w, __uint_as_float(v & 0xffff0000u), accA[2 * p + 1]);
                    }
                } else {
                    if (lane == 0) swB += w;
#pragma unroll
                    for (int p = 0; p < 8; p++) {
                        unsigned v = hp[p * 32 + lane];
                        accB[2 * p]     = fmaf(w, __uint_as_float(v << 16), accB[2 * p]);
                        accB[2 * p + 1] = fmaf(w, __uint_as_float(v & 0xffff0000u), accB[2 * p + 1]);
                    }
                }
            }
#pragma unroll
            for (int i = 0; i < 16; i++) {
                ctxs[wid * 512 + i * 32 + lane] = accA[i];
                ctxs[8192 + wid * 512 + i * 32 + lane] = accB[i];
            }
            if (lane == 0) { swarr[wid] = swA; swarr[16 + wid] = swB; }
            __syncthreads();
            // block reduce + global atomic accumulate
            {
                int col = tid;   // 512 columns
                float s0 = 0.f;
#pragma unroll
                for (int y = 0; y < 16; y++) s0 += ctxs[y * 512 + col];
                atomicAdd(&g_attc_f[b0 * 512 + col], s0);
                if (spans2) {
                    float s1 = 0.f;
#pragma unroll
                    for (int y = 0; y < 16; y++) s1 += ctxs[8192 + y * 512 + col];
                    atomicAdd(&g_attc_f[(b0 + 1) * 512 + col], s1);
                }
            }
            if (tid == 0) {
                float s = 0.f;
#pragma unroll
                for (int y = 0; y < 16; y++) s += swarr[y];
                atomicAdd(&g_sw[b0], s);
            }
            if (tid == 32 && spans2) {
                float s = 0.f;
#pragma unroll
                for (int y = 0; y < 16; y++) s += swarr[16 + y];
                atomicAdd(&g_sw[b0 + 1], s);
            }
        }
        gbar_arrive(++ep);

        // ===== P2: gates0 + cell0; ey/z0 staging prefetched under barrier latency =====
        if (bid < 128) {
            unsigned short* xs = (unsigned short*)smem;
            float* red = (float*)(smem + RED_OFF);
            uint4* xd = (uint4*)xs;
            // prefetch ey + z0 slices (independent of P1's output)
            for (int i = tid; i < 5120; i += NTH) {
                int b = i / 320, q = i - b * 320;
                if (q >= 128 && q < 192) continue;
                uint4 v;
                if (q < 128) v = ((const uint4*)g_eys_bf)[(size_t)(b * LL + l) * 128 + q];
                else         v = ((const uint4*)g_z0bf)[b * 128 + (q - 192)];
                xd[b * 321 + q] = v;
            }
            gbar_wait(ep);
            // attc slice (needs P1's atomics)
            for (int i = tid; i < 1024; i += NTH) {
                int b = i >> 6, q = 128 + (i & 63);
                int o = (q - 128) * 8;
                float4 f0 = *(const float4*)&g_attc_f[b * 512 + o];
                float4 f1 = *(const float4*)&g_attc_f[b * 512 + o + 4];
                float inv = __fdividef(1.0f, g_sw[b]);
                uint4 v;
                v.x = pk2bf(f0.x * inv, f0.y * inv);
                v.y = pk2bf(f0.z * inv, f0.w * inv);
                v.z = pk2bf(f1.x * inv, f1.y * inv);
                v.w = pk2bf(f1.z * inv, f1.w * inv);
                xd[b * 321 + q] = v;
            }
            __syncthreads();
            int g = wid & 3, ks = wid >> 2;
            float c[4] = {0.f, 0.f, 0.f, 0.f};
            warp_mma((const uint4*)g_W0F, 80, g * 128 + bid, ks * 20, 20, xs, XS0, lane, c);
            float* rw = &red[(wid * 32 + lane) * 4];
            rw[0] = c[0]; rw[1] = c[1]; rw[2] = c[2]; rw[3] = c[3];
            __syncthreads();
            if (tid < 128) {
                int b = tid >> 3, dl = tid & 7, d = bid * 8 + dl;
                int lr = (b & 7) * 4 + (dl >> 1);
                int rg = ((b >> 3) << 1) + (dl & 1);
                float gv4[4];
#pragma unroll
                for (int gg = 0; gg < 4; gg++) {
                    float s = 0.f;
#pragma unroll
                    for (int k2 = 0; k2 < 4; k2++) s += red[((k2 * 4 + gg) * 32 + lr) * 4 + rg];
                    gv4[gg] = s;
                }
                float gi = gv4[0] + g_b0[d], gf = gv4[1] + g_b0[1024 + d];
                float gg = gv4[2] + g_b0[2048 + d], go = gv4[3] + g_b0[3072 + d];
                int u = b * 1024 + d;
                float cc = sigm(gf) * g_c0[u] + sigm(gi) * tanh_ap(gg);
                float h = sigm(go) * tanh_ap(cc);
                g_c0[u] = cc;
                unsigned short hb = f2bf(h);
                g_z0bf[u] = hb;
                g_x1bf[b * 2048 + d] = hb;
                g_x1bf[b * 2048 + 1024 + d] = g_z1bf[u];
            }
        } else {
            gbar_wait(ep);
        }
        gbar(++ep);

        // ===== P3: gates1+cell1 (128) | dec_proj (16) | zero ctx accumulators (4) =====
        if (bid < 128) {
            unsigned short* xs = (unsigned short*)smem;
            float* red = (float*)(smem + RED_OFF);
            uint4* xd = (uint4*)xs;
            for (int i = tid; i < 4096; i += NTH) {
                int b = i >> 8, q = i & 255;
                xd[b * 257 + q] = ((const uint4*)g_x1bf)[b * 256 + q];
            }
            __syncthreads();
            int g = wid & 3, ks = wid >> 2;
            float c[4] = {0.f, 0.f, 0.f, 0.f};
            warp_mma((const uint4*)g_W1F, 64, g * 128 + bid, ks * 16, 16, xs, XS1, lane, c);
            float* rw = &red[(wid * 32 + lane) * 4];
            rw[0] = c[0]; rw[1] = c[1]; rw[2] = c[2]; rw[3] = c[3];
            __syncthreads();
            if (tid < 128) {
                int b = tid >> 3, dl = tid & 7, d = bid * 8 + dl;
                int lr = (b & 7) * 4 + (dl >> 1);
                int rg = ((b >> 3) << 1) + (dl & 1);
                float gv4[4];
#pragma unroll
                for (int gg = 0; gg < 4; gg++) {
                    float s = 0.f;
#pragma unroll
                    for (int k2 = 0; k2 < 4; k2++) s += red[((k2 * 4 + gg) * 32 + lr) * 4 + rg];
                    gv4[gg] = s;
                }
                float gi = gv4[0] + g_b1[d], gf = gv4[1] + g_b1[1024 + d];
                float gg = gv4[2] + g_b1[2048 + d], go = gv4[3] + g_b1[3072 + d];
                int u = b * 1024 + d;
                float cc = sigm(gf) * g_c1[u] + sigm(gi) * tanh_ap(gg);
                float h = sigm(go) * tanh_ap(cc);
                g_c1[u] = cc;
                unsigned short hb = f2bf(h);
                g_z1bf[u] = hb;
                g_zallbf[((size_t)b * LL + l) * 1024 + d] = hb;
            }
        } else if (bid < 144) {
            unsigned short* xs = (unsigned short*)smem;
            float* red = (float*)(smem + RED_OFF);
            uint4* xd = (uint4*)xs;
            for (int i = tid; i < 2048; i += NTH) {
                int b = i >> 7, q = i & 127;
                xd[b * 129 + q] = ((const uint4*)g_z0bf)[b * 128 + q];
            }
            __syncthreads();
            int ti = wid & 3, ks = wid >> 2;
            float c[4] = {0.f, 0.f, 0.f, 0.f};
            warp_mma((const uint4*)g_WdF, 32, (bid - 128) * 4 + ti, ks * 8, 8, xs, XSD, lane, c);
            float* rw = &red[(wid * 32 + lane) * 4];
            rw[0] = c[0]; rw[1] = c[1]; rw[2] = c[2]; rw[3] = c[3];
            __syncthreads();
            {
                int ti2 = tid >> 7, rem = tid & 127;
                int b = rem >> 3, al = rem & 7;
                int lr = (b & 7) * 4 + (al >> 1);
                int rg = ((b >> 3) << 1) + (al & 1);
                float s = 0.f;
#pragma unroll
                for (int k2 = 0; k2 < 4; k2++) s += red[((k2 * 4 + ti2) * 32 + lr) * 4 + rg];
                g_dp[b * 512 + (bid - 128) * 32 + ti2 * 8 + al] = s;
            }
        } else {
            // blocks 144-147: zero ctx accumulators for the NEXT step
            int base = (bid - 144) * 2048;
            for (int i = tid; i < 2048; i += NTH) g_attc_f[base + i] = 0.f;
            if (bid == 144 && tid < 16) g_sw[tid] = 0.f;
        }
        gbar(++ep);
    }
}

// ---------------- launch ----------------
extern "C" void kernel_launch(void* const* d_in, const int* in_sizes, int n_in,
                              void* d_out, int out_size) {
    const float* hs_pad = (const float*)d_in[0];
    const int*   hlens  = (const int*)d_in[1];
    const int*   ys_pad = (const int*)d_in[2];
    const float* embed  = (const float*)d_in[3];
    const float* W_ih0  = (const float*)d_in[4];
    const float* W_hh0  = (const float*)d_in[5];
    const float* b_ih0  = (const float*)d_in[6];
    const float* b_hh0  = (const float*)d_in[7];
    const float* W_ih1  = (const float*)d_in[8];
    const float* W_hh1  = (const float*)d_in[9];
    const float* b_ih1  = (const float*)d_in[10];
    const float* b_hh1  = (const float*)d_in[11];
    const float* W_enc  = (const float*)d_in[12];
    const float* b_enc  = (const float*)d_in[13];
    const float* W_dec  = (const float*)d_in[14];
    const float* gvec   = (const float*)d_in[15];
    const float* W_out  = (const float*)d_in[16];
    const float* b_out  = (const float*)d_in[17];
    float* out = (float*)d_out;

    unsigned short *d_wef, *d_wof, *d_hsbf, *d_zallbf, *d_pebf;
    cudaGetSymbolAddress((void**)&d_wef, g_WeF);
    cudaGetSymbolAddress((void**)&d_wof, g_WoF);
    cudaGetSymbolAddress((void**)&d_hsbf, g_hs_bf);
    cudaGetSymbolAddress((void**)&d_zallbf, g_zallbf);
    cudaGetSymbolAddress((void**)&d_pebf, g_preenc_bf);

    pack_all<<<(P4C + 255) / 256, 256>>>(W_ih0, W_hh0, W_ih1, W_hh1, W_enc, W_out, W_dec);
    prep_all<<<(BB * LL * DD + 255) / 256, 256>>>(hs_pad, b_ih0, b_hh0, b_ih1, b_hh1,
                                                  ys_pad, embed);

    // pre_enc = hs_bf @ W_enc^T + b_enc -> bf16   (M=12800, N=512, K=512)
    gemm_mma<2, 1><<<dim3(8, 400), 512, 32 * (512 + 8) * 2>>>(
        d_hsbf, (const uint4*)d_wef, b_enc, nullptr, d_pebf, BB * TT, AA, EE);

    // all 97 recurrent steps in one persistent kernel (3 barriers/step)
    cudaFuncSetAttribute(decoder_loop, cudaFuncAttributeMaxDynamicSharedMemorySize, SMEM_BYTES);
    decoder_loop<<<NBLK, NTH, SMEM_BYTES>>>(hlens, gvec);

    // fused logits GEMM + partial logsumexp (no logits materialization; 32x128 tiles)
    cudaFuncSetAttribute(gemm_logits_nll, cudaFuncAttributeMaxDynamicSharedMemorySize, LOGITS_SMEM);
    gemm_logits_nll<<<dim3(40, 49), 512, LOGITS_SMEM>>>(
        d_zallbf, (const uint4*)d_wof, b_out, ys_pad);

    finalize_nll<<<1, 512>>>(out);
}

// round 15
// speedup vs baseline: 1.4865x; 1.4865x over previous
#include <cuda_runtime.h>
#include <cuda_bf16.h>
#include <math.h>
#include <stdint.h>

#define BB 16
#define TT 800
#define EE 512
#define DD 1024
#define AA 512
#define OO 5000
#define LL 97
#define SOSEOS 4999
#define NBLK 148
#define NTH 512

// x staging strides (bf16 elems, +8 pad)
#define XS0 2568   // K0=2560
#define XS1 2056   // K1=2048
#define XSD 1032   // Kd=1024
#define RED_OFF 83968
#define SMEM_BYTES 92160
#define LOGITS_SMEM (32 * (DD + 8) * 2 + 32 * 132 * 4)

// ---------------- scratch ----------------
__device__ __align__(16) unsigned short g_preenc_bf[BB * TT * AA];
__device__ __align__(16) unsigned short g_hs_bf[BB * TT * EE];
__device__ __align__(16) unsigned short g_W0F[4096 * 2560];   // mma B-fragment layouts
__device__ __align__(16) unsigned short g_W1F[4096 * 2048];
__device__ __align__(16) unsigned short g_WdF[512 * 1024];
__device__ __align__(16) unsigned short g_WeF[512 * 512];
__device__ __align__(16) unsigned short g_WoF[5000 * 1024];
__device__ __align__(16) unsigned short g_eys_bf[BB * LL * DD];
__device__ __align__(16) unsigned short g_z0bf[BB * DD], g_z1bf[BB * DD];
__device__ __align__(16) unsigned short g_x1bf[BB * 2048];
__device__ __align__(16) unsigned short g_zallbf[BB * LL * DD];
__device__ float g_attc_f[BB * AA];       // unnormalized context accumulator (fp32 atomics)
__device__ float g_sw[BB];                // sum of softmax weights
__device__ float g_b0[4096], g_b1[4096];
__device__ float g_c0[BB * DD], g_c1[BB * DD];
__device__ float g_dp[BB * AA];
__device__ float g_pm2[BB * LL * 40], g_ps2[BB * LL * 40];
__device__ float g_tgt[BB * LL];
__device__ volatile unsigned g_arr[NBLK];
__device__ volatile unsigned g_rel;

// ---------------- helpers ----------------
__device__ __forceinline__ float tanh_ap(float x) {
    float y; asm("tanh.approx.f32 %0, %1;" : "=f"(y) : "f"(x)); return y;
}
__device__ __forceinline__ float sigm(float x) { return 1.0f / (1.0f + __expf(-x)); }
__device__ __forceinline__ unsigned short f2bf(float v) {
    return __bfloat16_as_ushort(__float2bfloat16_rn(v));
}
__device__ __forceinline__ unsigned pk2bf(float a, float b) {
    return (unsigned)f2bf(a) | ((unsigned)f2bf(b) << 16);
}

// device-wide barrier — PROVEN two-hop version (block0 detects, single release line)
__device__ __forceinline__ void gbar(unsigned ep) {
    __syncthreads();
    if (threadIdx.x == 0) {
        __threadfence();
        g_arr[blockIdx.x] = ep;
    }
    if (blockIdx.x == 0) {
        if (threadIdx.x < NBLK) {
            while (g_arr[threadIdx.x] < ep) { }
        }
        __syncthreads();
        if (threadIdx.x == 0) { __threadfence(); g_rel = ep; }
    }
    if (threadIdx.x == 0) {
        while (g_rel < ep) { }
        __threadfence();
    }
    __syncthreads();
}

// ---------------- prolog: pack ALL weights (coalesced, 32 k's / thread) ----------------
__device__ __forceinline__ void pack32(unsigned short* dst, int K, int j, int ktp,
                                       const float* __restrict__ Wa,
                                       const float* __restrict__ Wb, int Ka) {
    int jt = j >> 3, n = j & 7;
    unsigned short buf[32];
    int k0 = ktp * 32;
#pragma unroll
    for (int kk = 0; kk < 32; kk++) {
        int k = k0 + kk;
        float v = (k < Ka) ? Wa[(size_t)j * Ka + k] : Wb[(size_t)j * (K - Ka) + (k - Ka)];
        int kt = k >> 4, k16 = k & 15;
        int lane_off = (k16 & 7) >> 1;
        int comp = ((kt & 1) << 1) + (k16 >> 3);
        buf[lane_off * 8 + comp * 2 + (k16 & 1)] = f2bf(v);
    }
    size_t run = (((size_t)jt * (K >> 5) + ktp) * 32 + n * 4) * 8;
    uint4* d4 = (uint4*)(dst + run);
#pragma unroll
    for (int q = 0; q < 4; q++) d4[q] = ((const uint4*)buf)[q];
}
#define P0 327680            // W0: 4096*2560/32
#define P1 (P0 + 262144)     // W1: 4096*2048/32
#define P2C (P1 + 16384)     // Wd: 512*1024/32
#define P3C (P2C + 8192)     // We: 512*512/32
#define P4C (P3C + 160000)   // Wo: 5000*1024/32
__global__ void pack_all(const float* __restrict__ Wih0, const float* __restrict__ Whh0,
                         const float* __restrict__ Wih1, const float* __restrict__ Whh1,
                         const float* __restrict__ Wenc, const float* __restrict__ Wout,
                         const float* __restrict__ Wdec) {
    int i = blockIdx.x * 256 + threadIdx.x;
    if (i < P0) {
        int n = i & 7, rest = i >> 3;
        int ktp = rest % 80, jt = rest / 80;
        pack32(g_W0F, 2560, jt * 8 + n, ktp, Wih0, Whh0, 1536);
    } else if (i < P1) {
        int q = i - P0;
        int n = q & 7, rest = q >> 3;
        int ktp = rest % 64, jt = rest / 64;
        pack32(g_W1F, 2048, jt * 8 + n, ktp, Wih1, Whh1, 1024);
    } else if (i < P2C) {
        int q = i - P1;
        int n = q & 7, rest = q >> 3;
        int ktp = rest % 32, jt = rest / 32;
        pack32(g_WdF, 1024, jt * 8 + n, ktp, Wdec, Wdec, 1024);
    } else if (i < P3C) {
        int q = i - P2C;
        int n = q & 7, rest = q >> 3;
        int ktp = rest % 16, jt = rest / 16;
        pack32(g_WeF, 512, jt * 8 + n, ktp, Wenc, Wenc, 512);
    } else if (i < P4C) {
        int q = i - P3C;
        int n = q & 7, rest = q >> 3;
        int ktp = rest % 32, jt = rest / 32;
        pack32(g_WoF, 1024, jt * 8 + n, ktp, Wout, Wout, 1024);
    }
}

// merged small prolog (hs conversion vectorized: 8 elems/thread)
__global__ void prep_all(const float* __restrict__ hs,
                         const float* __restrict__ bih0, const float* __restrict__ bhh0,
                         const float* __restrict__ bih1, const float* __restrict__ bhh1,
                         const int* __restrict__ ys_pad, const float* __restrict__ embed) {
    int idx = blockIdx.x * 256 + threadIdx.x;
    if (idx < (BB * TT * EE) / 8) {
        const float4* s = (const float4*)hs + (size_t)idx * 2;
        float4 a = s[0], b = s[1];
        uint4 v;
        v.x = pk2bf(a.x, a.y); v.y = pk2bf(a.z, a.w);
        v.z = pk2bf(b.x, b.y); v.w = pk2bf(b.z, b.w);
        ((uint4*)g_hs_bf)[idx] = v;
    }
    if (idx < 4096) {
        g_b0[idx] = bih0[idx] + bhh0[idx];
        g_b1[idx] = bih1[idx] + bhh1[idx];
    }
    if (idx < BB * DD) {
        g_c0[idx] = 0.f; g_c1[idx] = 0.f;
        g_z0bf[idx] = 0; g_z1bf[idx] = 0;
    }
    if (idx < BB * AA) { g_dp[idx] = 0.f; g_attc_f[idx] = 0.f; }
    if (idx < BB) g_sw[idx] = 0.f;
    if (idx < NBLK) g_arr[idx] = 0u;
    if (idx == 0) g_rel = 0u;
    if (idx < BB * LL * DD) {
        int m = idx >> 10, d = idx & 1023;
        int b = m / LL, l = m % LL;
        int tok = (l == 0) ? SOSEOS : ys_pad[b * 96 + l - 1];
        g_eys_bf[idx] = f2bf(embed[(size_t)tok * DD + d]);
    }
}

// ---------------- warp-level mma over one n8 tile, k-slice ----------------
__device__ __forceinline__ void warp_mma(const uint4* __restrict__ wf, int KT32, int jt,
                                         int ktp0, int nktp, const unsigned short* xs,
                                         int XSTR, int lane, float* c) {
    int m = lane >> 3, r = lane & 7;
    int row = r + ((m & 1) << 3);
    int colh = m >> 1;
    unsigned sbase = (unsigned)__cvta_generic_to_shared(xs) + (unsigned)((row * XSTR + colh * 8) * 2);
    const uint4* wp = wf + (size_t)jt * KT32 * 32 + lane;
#pragma unroll 4
    for (int t = 0; t < nktp; t++) {
        int ktp = ktp0 + t;
        unsigned a0,a1,a2,a3, e0,e1,e2,e3;
        unsigned addr0 = sbase + (unsigned)(ktp * 64);
        asm volatile("ldmatrix.sync.aligned.m8n8.x4.shared.b16 {%0,%1,%2,%3}, [%4];"
            : "=r"(a0),"=r"(a1),"=r"(a2),"=r"(a3) : "r"(addr0));
        asm volatile("ldmatrix.sync.aligned.m8n8.x4.shared.b16 {%0,%1,%2,%3}, [%4];"
            : "=r"(e0),"=r"(e1),"=r"(e2),"=r"(e3) : "r"(addr0 + 32u));
        uint4 wv = wp[(size_t)ktp * 32];
        asm volatile("mma.sync.aligned.m16n8k16.row.col.f32.bf16.bf16.f32 "
            "{%0,%1,%2,%3}, {%4,%5,%6,%7}, {%8,%9}, {%0,%1,%2,%3};"
            : "+f"(c[0]),"+f"(c[1]),"+f"(c[2]),"+f"(c[3])
            : "r"(a0),"r"(a1),"r"(a2),"r"(a3), "r"(wv.x),"r"(wv.y));
        asm volatile("mma.sync.aligned.m16n8k16.row.col.f32.bf16.bf16.f32 "
            "{%0,%1,%2,%3}, {%4,%5,%6,%7}, {%8,%9}, {%0,%1,%2,%3};"
            : "+f"(c[0]),"+f"(c[1]),"+f"(c[2]),"+f"(c[3])
            : "r"(e0),"r"(e1),"r"(e2),"r"(e3), "r"(wv.z),"r"(wv.w));
    }
}

// ---------------- tensor-core GEMM (pre_enc): Cbf[M,N] = A x Bfrag^T + bias ----------------
template <int MSL, int STORE_BF>
__global__ __launch_bounds__(512) void gemm_mma(const unsigned short* __restrict__ A,
        const uint4* __restrict__ BF, const float* __restrict__ bias,
        float* __restrict__ C, unsigned short* __restrict__ Cbf,
        int M, int N, int K) {
    extern __shared__ __align__(16) unsigned short xsd[];
    const int XSTR = K + 8;
    const int tid = threadIdx.x, lane = tid & 31, wid = tid >> 5;
    const int MT = MSL * 16, NTILE = 16 / MSL;
    int m0 = blockIdx.y * MT;
    int n0 = blockIdx.x * NTILE * 8;
    int kq = K >> 3;
    const uint4* Ag = (const uint4*)A;
    for (int i = tid; i < MT * kq; i += 512) {
        int r = i / kq, q = i - r * kq;
        ((uint4*)(xsd + r * XSTR))[q] = Ag[(size_t)(m0 + r) * kq + q];
    }
    __syncthreads();
    int mi = wid / NTILE, nj = wid % NTILE;
    int jt = (n0 >> 3) + nj;
    if (jt * 8 < N) {
        float c[4] = {0.f, 0.f, 0.f, 0.f};
        warp_mma(BF, K >> 5, jt, 0, K >> 5, xsd + mi * 16 * XSTR, XSTR, lane, c);
        int row0 = m0 + mi * 16;
#pragma unroll
        for (int r = 0; r < 4; r++) {
            int row = row0 + (lane >> 2) + 8 * (r >> 1);
            int col = jt * 8 + (lane & 3) * 2 + (r & 1);
            if (col < N) {
                float v = c[r] + bias[col];
                if (STORE_BF) Cbf[(size_t)row * N + col] = f2bf(v);
                else          C[(size_t)row * N + col] = v;
            }
        }
    }
}

// ---------------- fused logits GEMM + partial logsumexp NLL (32 rows x 128 cols/block) ----------------
__global__ __launch_bounds__(512) void gemm_logits_nll(const unsigned short* __restrict__ A,
        const uint4* __restrict__ BF, const float* __restrict__ bias,
        const int* __restrict__ ys_pad) {
    extern __shared__ __align__(16) unsigned short xsd[];
    const int XSTR = DD + 8;                       // 1032
    float* sl = (float*)(xsd + 32 * XSTR);         // [32][132] fp32
    const int tid = threadIdx.x, lane = tid & 31, wid = tid >> 5;
    int m0 = blockIdx.y * 32, bx = blockIdx.x;
    const uint4* Ag = (const uint4*)A;
    for (int i = tid; i < 32 * 128; i += 512) {
        int r = i >> 7, q = i & 127;
        int row = min(m0 + r, BB * LL - 1);
        ((uint4*)(xsd + r * XSTR))[q] = Ag[(size_t)row * 128 + q];
    }
    __syncthreads();
    int mi = wid >> 3, nj = wid & 7;
    const unsigned short* xrow = xsd + mi * 16 * XSTR;
#pragma unroll
    for (int tt = 0; tt < 2; tt++) {
        int jt = bx * 16 + nj * 2 + tt;
        float c[4] = {0.f, 0.f, 0.f, 0.f};
        if (jt * 8 < OO)
            warp_mma(BF, 32, jt, 0, 32, xrow, XSTR, lane, c);
#pragma unroll
        for (int r = 0; r < 4; r++) {
            int row = mi * 16 + (lane >> 2) + 8 * (r >> 1);
            int coll = (nj * 2 + tt) * 8 + (lane & 3) * 2 + (r & 1);
            int gcol = bx * 128 + coll;
            sl[row * 132 + coll] = (gcol < OO) ? c[r] + bias[gcol] : -1e30f;
        }
    }
    __syncthreads();
#pragma unroll
    for (int rr2 = 0; rr2 < 2; rr2++) {
        int row = wid * 2 + rr2;     // 32 rows over 16 warps
        float v[4];
#pragma unroll
        for (int i = 0; i < 4; i++) v[i] = sl[row * 132 + lane * 4 + i];
        float mx = fmaxf(fmaxf(v[0], v[1]), fmaxf(v[2], v[3]));
#pragma unroll
        for (int o = 16; o; o >>= 1) mx = fmaxf(mx, __shfl_xor_sync(~0u, mx, o));
        float s = __expf(v[0] - mx) + __expf(v[1] - mx) + __expf(v[2] - mx) + __expf(v[3] - mx);
#pragma unroll
        for (int o = 16; o; o >>= 1) s += __shfl_xor_sync(~0u, s, o);
        int grow = m0 + row;
        if (lane == 0 && grow < BB * LL) {
            g_pm2[grow * 40 + bx] = mx;
            g_ps2[grow * 40 + bx] = s;
            int b = grow / LL, l = grow % LL;
            int tgt = (l < 96) ? ys_pad[b * 96 + l] : SOSEOS;
            if (tgt >= bx * 128 && tgt < bx * 128 + 128)
                g_tgt[grow] = sl[row * 132 + (tgt - bx * 128)];
        }
    }
}

__global__ __launch_bounds__(512) void finalize_nll(float* out) {
    __shared__ float red[512];
    int tid = threadIdx.x;
    float acc = 0.f;
    for (int row = tid; row < BB * LL; row += 512) {
        float M = -1e30f;
#pragma unroll 8
        for (int j = 0; j < 40; j++) M = fmaxf(M, g_pm2[row * 40 + j]);
        float S = 0.f;
#pragma unroll 8
        for (int j = 0; j < 40; j++) S += g_ps2[row * 40 + j] * __expf(g_pm2[row * 40 + j] - M);
        acc += logf(S) + M - g_tgt[row];
    }
    red[tid] = acc; __syncthreads();
    for (int s = 256; s; s >>= 1) { if (tid < s) red[tid] += red[tid + s]; __syncthreads(); }
    if (tid == 0) out[0] = red[0] * (96.0f / (float)(BB * LL));
}

// ---------------- persistent decoder loop: 3 phases/step (PROVEN 2526-us structure) ----------------
extern "C" __global__ void __launch_bounds__(NTH, 1)
decoder_loop(const int* __restrict__ hlens, const float* __restrict__ gvec) {
    extern __shared__ __align__(16) char smem[];
    const int bid = blockIdx.x, tid = threadIdx.x;
    const int lane = tid & 31, wid = tid >> 5;
    unsigned ep = 0;

    for (int l = 0; l < LL; l++) {
        // ===== P1: scores + exp (no-max) + unnormalized partial context, all fused =====
        {
            int r0 = bid * 86 + min(bid, 72);
            int nr = 86 + (bid < 72 ? 1 : 0);
            int b0 = r0 / 800;
            bool spans2 = ((r0 + nr - 1) / 800) > b0;
            int hl0 = hlens[b0];
            int hl1 = (b0 + 1 < 16) ? hlens[b0 + 1] : 0;
            unsigned* dp2 = (unsigned*)smem;                  // [2][256] packed bf16x2
            float2* gv2 = (float2*)(smem + 2048);             // [256]
            float* ctxs = (float*)(smem + 4096);              // [2][16][512] fp32
            float* swarr = (float*)(smem + 4096 + 65536);     // [2][16]
            if (tid < 512) {
                int s = tid >> 8, q = tid & 255;
                int bb = b0 + s;
                unsigned pk = 0;
                if (bb < 16) pk = pk2bf(g_dp[bb * 512 + 2 * q], g_dp[bb * 512 + 2 * q + 1]);
                dp2[tid] = pk;
                if (tid < 256) gv2[tid] = make_float2(gvec[2 * tid], gvec[2 * tid + 1]);
            }
            __syncthreads();
            float accA[16], accB[16];
#pragma unroll
            for (int i = 0; i < 16; i++) { accA[i] = 0.f; accB[i] = 0.f; }
            float swA = 0.f, swB = 0.f;
            const unsigned* hsb = (const unsigned*)g_hs_bf;
            for (int r = r0 + wid; r < r0 + nr; r += 16) {
                int b = (r >= (b0 + 1) * 800) ? (b0 + 1) : b0;
                int t = r - b * 800;
                const unsigned* pe = (const unsigned*)g_preenc_bf + (size_t)r * 256;
                const unsigned* dpb = dp2 + (b - b0) * 256;
                float acc = 0.f;
#pragma unroll
                for (int p = 0; p < 8; p++) {
                    int q = lane + 32 * p;
                    unsigned v = pe[q];
                    unsigned d = dpb[q];
                    unsigned sm2, t2;
                    asm("add.rn.bf16x2 %0, %1, %2;" : "=r"(sm2) : "r"(v), "r"(d));
                    asm("tanh.approx.bf16x2 %0, %1;" : "=r"(t2) : "r"(sm2));
                    float lo = __uint_as_float(t2 << 16);
                    float hi = __uint_as_float(t2 & 0xffff0000u);
                    float2 g2 = gv2[q];
                    acc = fmaf(g2.x, lo, fmaf(g2.y, hi, acc));
                }
#pragma unroll
                for (int o = 16; o; o >>= 1) acc += __shfl_xor_sync(~0u, acc, o);
                int hl = (b == b0) ? hl0 : hl1;
                float w = (t < hl) ? __expf(2.0f * acc) : 0.f;
                const unsigned* hp = hsb + (size_t)r * 256;
                if (b == b0) {
                    if (lane == 0) swA += w;
#pragma unroll
                    for (int p = 0; p < 8; p++) {
                        unsigned v = hp[p * 32 + lane];
                        accA[2 * p]     = fmaf(w, __uint_as_float(v << 16), accA[2 * p]);
                        accA[2 * p + 1] = fmaf(w, __uint_as_float(v & 0xffff0000u), accA[2 * p + 1]);
                    }
                } else {
                    if (lane == 0) swB += w;
#pragma unroll
                    for (int p = 0; p < 8; p++) {
                        unsigned v = hp[p * 32 + lane];
                        accB[2 * p]     = fmaf(w, __uint_as_float(v << 16), accB[2 * p]);
                        accB[2 * p + 1] = fmaf(w, __uint_as_float(v & 0xffff0000u), accB[2 * p + 1]);
                    }
                }
            }
#pragma unroll
            for (int i = 0; i < 16; i++) {
                ctxs[wid * 512 + i * 32 + lane] = accA[i];
                ctxs[8192 + wid * 512 + i * 32 + lane] = accB[i];
            }
            if (lane == 0) { swarr[wid] = swA; swarr[16 + wid] = swB; }
            __syncthreads();
            // block reduce + global atomic accumulate
            {
                int col = tid;   // 512 columns
                float s0 = 0.f;
#pragma unroll
                for (int y = 0; y < 16; y++) s0 += ctxs[y * 512 + col];
                atomicAdd(&g_attc_f[b0 * 512 + col], s0);
                if (spans2) {
                    float s1 = 0.f;
#pragma unroll
                    for (int y = 0; y < 16; y++) s1 += ctxs[8192 + y * 512 + col];
                    atomicAdd(&g_attc_f[(b0 + 1) * 512 + col], s1);
                }
            }
            if (tid == 0) {
                float s = 0.f;
#pragma unroll
                for (int y = 0; y < 16; y++) s += swarr[y];
                atomicAdd(&g_sw[b0], s);
            }
            if (tid == 32 && spans2) {
                float s = 0.f;
#pragma unroll
                for (int y = 0; y < 16; y++) s += swarr[16 + y];
                atomicAdd(&g_sw[b0 + 1], s);
            }
        }
        gbar(++ep);

        // ===== P2: gates0 + cell0 (128 blocks x 8 d, full K=2560); ctx normalize in staging =====
        if (bid < 128) {
            unsigned short* xs = (unsigned short*)smem;
            float* red = (float*)(smem + RED_OFF);
            uint4* xd = (uint4*)xs;
            for (int i = tid; i < 5120; i += NTH) {
                int b = i / 320, q = i - b * 320;
                uint4 v;
                if (q < 128) {
                    v = ((const uint4*)g_eys_bf)[(size_t)(b * LL + l) * 128 + q];
                } else if (q < 192) {
                    int o = (q - 128) * 8;
                    float4 f0 = *(const float4*)&g_attc_f[b * 512 + o];
                    float4 f1 = *(const float4*)&g_attc_f[b * 512 + o + 4];
                    float inv = __fdividef(1.0f, g_sw[b]);
                    v.x = pk2bf(f0.x * inv, f0.y * inv);
                    v.y = pk2bf(f0.z * inv, f0.w * inv);
                    v.z = pk2bf(f1.x * inv, f1.y * inv);
                    v.w = pk2bf(f1.z * inv, f1.w * inv);
                } else {
                    v = ((const uint4*)g_z0bf)[b * 128 + (q - 192)];
                }
                xd[b * 321 + q] = v;
            }
            __syncthreads();
            int g = wid & 3, ks = wid >> 2;
            float c[4] = {0.f, 0.f, 0.f, 0.f};
            warp_mma((const uint4*)g_W0F, 80, g * 128 + bid, ks * 20, 20, xs, XS0, lane, c);
            float* rw = &red[(wid * 32 + lane) * 4];
            rw[0] = c[0]; rw[1] = c[1]; rw[2] = c[2]; rw[3] = c[3];
            __syncthreads();
            if (tid < 128) {
                int b = tid >> 3, dl = tid & 7, d = bid * 8 + dl;
                int lr = (b & 7) * 4 + (dl >> 1);
                int rg = ((b >> 3) << 1) + (dl & 1);
                float gv4[4];
#pragma unroll
                for (int gg = 0; gg < 4; gg++) {
                    float s = 0.f;
#pragma unroll
                    for (int k2 = 0; k2 < 4; k2++) s += red[((k2 * 4 + gg) * 32 + lr) * 4 + rg];
                    gv4[gg] = s;
                }
                float gi = gv4[0] + g_b0[d], gf = gv4[1] + g_b0[1024 + d];
                float gg = gv4[2] + g_b0[2048 + d], go = gv4[3] + g_b0[3072 + d];
                int u = b * 1024 + d;
                float cc = sigm(gf) * g_c0[u] + sigm(gi) * tanh_ap(gg);
                float h = sigm(go) * tanh_ap(cc);
                g_c0[u] = cc;
                unsigned short hb = f2bf(h);
                g_z0bf[u] = hb;
                g_x1bf[b * 2048 + d] = hb;
                g_x1bf[b * 2048 + 1024 + d] = g_z1bf[u];
            }
        }
        gbar(++ep);

        // ===== P3: gates1+cell1 (128) | dec_proj (16) | zero ctx accumulators (4) =====
        if (bid < 128) {
            unsigned short* xs = (unsigned short*)smem;
            float* red = (float*)(smem + RED_OFF);
            uint4* xd = (uint4*)xs;
            for (int i = tid; i < 4096; i += NTH) {
                int b = i >> 8, q = i & 255;
                xd[b * 257 + q] = ((const uint4*)g_x1bf)[b * 256 + q];
            }
            __syncthreads();
            int g = wid & 3, ks = wid >> 2;
            float c[4] = {0.f, 0.f, 0.f, 0.f};
            warp_mma((const uint4*)g_W1F, 64, g * 128 + bid, ks * 16, 16, xs, XS1, lane, c);
            float* rw = &red[(wid * 32 + lane) * 4];
            rw[0] = c[0]; rw[1] = c[1]; rw[2] = c[2]; rw[3] = c[3];
            __syncthreads();
            if (tid < 128) {
                int b = tid >> 3, dl = tid & 7, d = bid * 8 + dl;
                int lr = (b & 7) * 4 + (dl >> 1);
                int rg = ((b >> 3) << 1) + (dl & 1);
                float gv4[4];
#pragma unroll
                for (int gg = 0; gg < 4; gg++) {
                    float s = 0.f;
#pragma unroll
                    for (int k2 = 0; k2 < 4; k2++) s += red[((k2 * 4 + gg) * 32 + lr) * 4 + rg];
                    gv4[gg] = s;
                }
                float gi = gv4[0] + g_b1[d], gf = gv4[1] + g_b1[1024 + d];
                float gg = gv4[2] + g_b1[2048 + d], go = gv4[3] + g_b1[3072 + d];
                int u = b * 1024 + d;
                float cc = sigm(gf) * g_c1[u] + sigm(gi) * tanh_ap(gg);
                float h = sigm(go) * tanh_ap(cc);
                g_c1[u] = cc;
                unsigned short hb = f2bf(h);
                g_z1bf[u] = hb;
                g_zallbf[((size_t)b * LL + l) * 1024 + d] = hb;
            }
        } else if (bid < 144) {
            unsigned short* xs = (unsigned short*)smem;
            float* red = (float*)(smem + RED_OFF);
            uint4* xd = (uint4*)xs;
            for (int i = tid; i < 2048; i += NTH) {
                int b = i >> 7, q = i & 127;
                xd[b * 129 + q] = ((const uint4*)g_z0bf)[b * 128 + q];
            }
            __syncthreads();
            int ti = wid & 3, ks = wid >> 2;
            float c[4] = {0.f, 0.f, 0.f, 0.f};
            warp_mma((const uint4*)g_WdF, 32, (bid - 128) * 4 + ti, ks * 8, 8, xs, XSD, lane, c);
            float* rw = &red[(wid * 32 + lane) * 4];
            rw[0] = c[0]; rw[1] = c[1]; rw[2] = c[2]; rw[3] = c[3];
            __syncthreads();
            {
                int ti2 = tid >> 7, rem = tid & 127;
                int b = rem >> 3, al = rem & 7;
                int lr = (b & 7) * 4 + (al >> 1);
                int rg = ((b >> 3) << 1) + (al & 1);
                float s = 0.f;
#pragma unroll
                for (int k2 = 0; k2 < 4; k2++) s += red[((k2 * 4 + ti2) * 32 + lr) * 4 + rg];
                g_dp[b * 512 + (bid - 128) * 32 + ti2 * 8 + al] = s;
            }
        } else {
            // blocks 144-147: zero ctx accumulators for the NEXT step
            int base = (bid - 144) * 2048;
            for (int i = tid; i < 2048; i += NTH) g_attc_f[base + i] = 0.f;
            if (bid == 144 && tid < 16) g_sw[tid] = 0.f;
        }
        gbar(++ep);
    }
}

// ---------------- launch ----------------
extern "C" void kernel_launch(void* const* d_in, const int* in_sizes, int n_in,
                              void* d_out, int out_size) {
    const float* hs_pad = (const float*)d_in[0];
    const int*   hlens  = (const int*)d_in[1];
    const int*   ys_pad = (const int*)d_in[2];
    const float* embed  = (const float*)d_in[3];
    const float* W_ih0  = (const float*)d_in[4];
    const float* W_hh0  = (const float*)d_in[5];
    const float* b_ih0  = (const float*)d_in[6];
    const float* b_hh0  = (const float*)d_in[7];
    const float* W_ih1  = (const float*)d_in[8];
    const float* W_hh1  = (const float*)d_in[9];
    const float* b_ih1  = (const float*)d_in[10];
    const float* b_hh1  = (const float*)d_in[11];
    const float* W_enc  = (const float*)d_in[12];
    const float* b_enc  = (const float*)d_in[13];
    const float* W_dec  = (const float*)d_in[14];
    const float* gvec   = (const float*)d_in[15];
    const float* W_out  = (const float*)d_in[16];
    const float* b_out  = (const float*)d_in[17];
    float* out = (float*)d_out;

    unsigned short *d_wef, *d_wof, *d_hsbf, *d_zallbf, *d_pebf;
    cudaGetSymbolAddress((void**)&d_wef, g_WeF);
    cudaGetSymbolAddress((void**)&d_wof, g_WoF);
    cudaGetSymbolAddress((void**)&d_hsbf, g_hs_bf);
    cudaGetSymbolAddress((void**)&d_zallbf, g_zallbf);
    cudaGetSymbolAddress((void**)&d_pebf, g_preenc_bf);

    pack_all<<<(P4C + 255) / 256, 256>>>(W_ih0, W_hh0, W_ih1, W_hh1, W_enc, W_out, W_dec);
    prep_all<<<(BB * LL * DD + 255) / 256, 256>>>(hs_pad, b_ih0, b_hh0, b_ih1, b_hh1,
                                                  ys_pad, embed);

    // pre_enc = hs_bf @ W_enc^T + b_enc -> bf16   (M=12800, N=512, K=512)
    gemm_mma<2, 1><<<dim3(8, 400), 512, 32 * (512 + 8) * 2>>>(
        d_hsbf, (const uint4*)d_wef, b_enc, nullptr, d_pebf, BB * TT, AA, EE);

    // all 97 recurrent steps in one persistent kernel (3 barriers/step)
    cudaFuncSetAttribute(decoder_loop, cudaFuncAttributeMaxDynamicSharedMemorySize, SMEM_BYTES);
    decoder_loop<<<NBLK, NTH, SMEM_BYTES>>>(hlens, gvec);

    // fused logits GEMM + partial logsumexp (no logits materialization; 32x128 tiles)
    cudaFuncSetAttribute(gemm_logits_nll, cudaFuncAttributeMaxDynamicSharedMemorySize, LOGITS_SMEM);
    gemm_logits_nll<<<dim3(40, 49), 512, LOGITS_SMEM>>>(
        d_zallbf, (const uint4*)d_wof, b_out, ys_pad);

    finalize_nll<<<1, 512>>>(out);
}